// round 11
// baseline (speedup 1.0000x reference)
#include <cuda_runtime.h>
#include <cuda_fp16.h>
#include <float.h>

#define C_DIM 512
#define H_DIM 50
#define W_DIM 75
#define HW_DIM (H_DIM * W_DIM)
#define NROI 512
#define PRE 14
#define PADH 264   // stage row stride in halves (= 528B, 16B-aligned)

// channels-last fp16 copy of the feature map: [H*W, C]
__device__ __align__(16) __half g_featT[HW_DIM * C_DIM];

// -------------------------------------------------------------------------
// Tiled transpose + fp16 quantize: bottom [C, H*W] -> g_featT [H*W, C]
// Block covers 64 channels x 32 hw; stores half2 (coalesced 128B rows).
// -------------------------------------------------------------------------
__global__ void transpose_kernel(const float* __restrict__ in) {
    __shared__ float tile[64][33];
    int hw0 = blockIdx.x * 32;
    int c0  = blockIdx.y * 64;
    int tx = threadIdx.x, ty = threadIdx.y;

    #pragma unroll
    for (int j = 0; j < 64; j += 8) {
        int hw = hw0 + tx;
        int c  = c0 + ty + j;
        if (hw < HW_DIM) tile[ty + j][tx] = in[c * HW_DIM + hw];
    }
    __syncthreads();
    #pragma unroll
    for (int j = 0; j < 32; j += 8) {
        int hw = hw0 + ty + j;
        if (hw < HW_DIM) {
            __half2 v = __floats2half2_rn(tile[2 * tx][ty + j],
                                          tile[2 * tx + 1][ty + j]);
            *reinterpret_cast<__half2*>(&g_featT[hw * C_DIM + c0 + 2 * tx]) = v;
        }
    }
}

// -------------------------------------------------------------------------
// Main kernel: grid (512 rois, 2 channel-halves), 128 threads (4 warps).
// Lane owns 8 consecutive channels (16B fp16 LDG.128 = 4 half2); warp covers
// a 256-channel half; the 4 warps split the 49 output pixels round-robin.
// Bilinear sample = corner-sum in half2 with fp32-computed corner weights.
// occ 8 (<=64 regs) for maximum resident warps; simple 4x4-load loop (ptxas
// batches the gathers; manual pipelining measured slower).
// -------------------------------------------------------------------------
__global__ __launch_bounds__(128, 8) void roi_pool_kernel(
    const float* __restrict__ rois, float* __restrict__ out) {

    // Packed corner tables: (.x = off0 bits, .y = off1 bits, .z = w0, .w = w1),
    // offsets in 8-channel (uint4) units.
    __shared__ float4 tabx[PRE], taby[PRE];
    __shared__ __align__(16) __half stage[49 * PADH];

    const int n = blockIdx.x;
    const int t = threadIdx.x;

    // ---- per-ROI corner tables (threads 0..27) ----
    if (t < 2 * PRE) {
        const int axis = (t >= PRE);          // 0 = x, 1 = y
        const int i = axis ? (t - PRE) : t;
        const float lo = rois[n * 5 + (axis ? 2 : 1)] * (1.0f / 16.0f);
        const float hi = rois[n * 5 + (axis ? 4 : 3)] * (1.0f / 16.0f);
        const int D = axis ? H_DIM : W_DIM;

        // replicate reference math exactly
        float s  = (hi - lo) / (float)(D - 1);
        float tt = (lo + hi - (float)(D - 1)) / (float)(D - 1);
        float base = -1.0f + (float)i * (2.0f / 13.0f);
        float g  = s * base + tt;
        float xc = (g + 1.0f) * 0.5f * (float)(D - 1);

        float f0 = floorf(xc);
        int   i0 = (int)f0;
        float w1 = xc - f0;
        float w0 = 1.0f - w1;
        float v0 = (i0 >= 0 && i0 <= D - 1) ? 1.0f : 0.0f;
        float v1 = (i0 + 1 >= 0 && i0 + 1 <= D - 1) ? 1.0f : 0.0f;
        int c0 = min(max(i0, 0), D - 1);
        int c1 = min(max(i0 + 1, 0), D - 1);

        int mul = axis ? (W_DIM * (C_DIM / 8)) : (C_DIM / 8);
        float4 e;
        e.x = __int_as_float(c0 * mul);
        e.y = __int_as_float(c1 * mul);
        e.z = w0 * v0;
        e.w = w1 * v1;
        if (axis) taby[i] = e; else tabx[i] = e;
    }
    __syncthreads();

    const int w    = t >> 5;
    const int lane = t & 31;
    const uint4* __restrict__ fb =
        (const uint4*)g_featT + blockIdx.y * 32 + lane;

    const __half2 HMIN = __float2half2_rn(-60000.0f);

    for (int p = w; p < 49; p += 4) {
        const int py = p / 7;
        const int px = p - py * 7;

        const float4 tx0 = tabx[2 * px];
        const float4 tx1 = tabx[2 * px + 1];
        const float4 ty0 = taby[2 * py];
        const float4 ty1 = taby[2 * py + 1];

        __half2 m0 = HMIN, m1 = HMIN, m2 = HMIN, m3 = HMIN;

        #pragma unroll
        for (int dy = 0; dy < 2; dy++) {
            const float4 ty = dy ? ty1 : ty0;
            const int oy0 = __float_as_int(ty.x);
            const int oy1 = __float_as_int(ty.y);
            const float wy0 = ty.z, wy1 = ty.w;
            #pragma unroll
            for (int dx = 0; dx < 2; dx++) {
                const float4 tx = dx ? tx1 : tx0;
                const int ox0 = __float_as_int(tx.x);
                const int ox1 = __float_as_int(tx.y);

                // 4 independent 16B gathers (8 fp16 channels each)
                uint4 r00 = fb[oy0 + ox0];
                uint4 r01 = fb[oy0 + ox1];
                uint4 r10 = fb[oy1 + ox0];
                uint4 r11 = fb[oy1 + ox1];

                // corner weights: fp32 products, broadcast to half2
                const float wx0 = tx.z, wx1 = tx.w;
                const __half2 w00 = __float2half2_rn(wy0 * wx0);
                const __half2 w01 = __float2half2_rn(wy0 * wx1);
                const __half2 w10 = __float2half2_rn(wy1 * wx0);
                const __half2 w11 = __float2half2_rn(wy1 * wx1);

                const __half2* h00 = reinterpret_cast<const __half2*>(&r00);
                const __half2* h01 = reinterpret_cast<const __half2*>(&r01);
                const __half2* h10 = reinterpret_cast<const __half2*>(&r10);
                const __half2* h11 = reinterpret_cast<const __half2*>(&r11);

                __half2 v0 = __hmul2(h00[0], w00);
                __half2 v1 = __hmul2(h00[1], w00);
                __half2 v2 = __hmul2(h00[2], w00);
                __half2 v3 = __hmul2(h00[3], w00);
                v0 = __hfma2(h01[0], w01, v0);
                v1 = __hfma2(h01[1], w01, v1);
                v2 = __hfma2(h01[2], w01, v2);
                v3 = __hfma2(h01[3], w01, v3);
                v0 = __hfma2(h10[0], w10, v0);
                v1 = __hfma2(h10[1], w10, v1);
                v2 = __hfma2(h10[2], w10, v2);
                v3 = __hfma2(h10[3], w10, v3);
                v0 = __hfma2(h11[0], w11, v0);
                v1 = __hfma2(h11[1], w11, v1);
                v2 = __hfma2(h11[2], w11, v2);
                v3 = __hfma2(h11[3], w11, v3);

                m0 = __hmax2(m0, v0);
                m1 = __hmax2(m1, v1);
                m2 = __hmax2(m2, v2);
                m3 = __hmax2(m3, v3);
            }
        }

        // pixel-major fp16 stage: 16B STS, lane-consecutive -> conflict-free
        uint4 pk;
        pk.x = *reinterpret_cast<unsigned int*>(&m0);
        pk.y = *reinterpret_cast<unsigned int*>(&m1);
        pk.z = *reinterpret_cast<unsigned int*>(&m2);
        pk.w = *reinterpret_cast<unsigned int*>(&m3);
        *reinterpret_cast<uint4*>(&stage[p * PADH + lane * 8]) = pk;
    }
    __syncthreads();

    // ---- coalesced writeback: 256*49 = 12544 floats, idx = t + k*128
    // walked incrementally over (c, p), p fastest.
    float* __restrict__ ob = out + (size_t)n * (C_DIM * 49)
                                 + (size_t)blockIdx.y * (256 * 49);
    int c = t / 49;
    int p = t - c * 49;
    #pragma unroll 7
    for (int k = 0; k < 98; k++) {
        ob[t + k * 128] = __half2float(stage[p * PADH + c]);
        p += 30; c += 2;              // advance by 128 = 2*49 + 30
        if (p >= 49) { p -= 49; c += 1; }
    }
}

// -------------------------------------------------------------------------
extern "C" void kernel_launch(void* const* d_in, const int* in_sizes, int n_in,
                              void* d_out, int out_size) {
    const float* bottom = (const float*)d_in[0];
    const float* rois   = (const float*)d_in[1];
    if (n_in >= 2 && in_sizes[0] == NROI * 5) {
        bottom = (const float*)d_in[1];
        rois   = (const float*)d_in[0];
    }
    float* out = (float*)d_out;

    dim3 tgrid((HW_DIM + 31) / 32, C_DIM / 64);
    transpose_kernel<<<tgrid, dim3(32, 8)>>>(bottom);

    dim3 rgrid(NROI, 2);
    roi_pool_kernel<<<rgrid, 128>>>(rois, out);
}

// round 12
// speedup vs baseline: 1.5031x; 1.5031x over previous
#include <cuda_runtime.h>
#include <cuda_fp16.h>
#include <float.h>

#define C_DIM 512
#define H_DIM 50
#define W_DIM 75
#define HW_DIM (H_DIM * W_DIM)
#define NROI 512
#define PRE 14
#define NSAMP (PRE * PRE)
#define PADH 264   // stage row stride in halves (= 528B, 16B-aligned)

// channels-last fp16 copy of the feature map: [H*W, C]
__device__ __align__(16) __half g_featT[HW_DIM * C_DIM];

// -------------------------------------------------------------------------
// Tiled transpose + fp16 quantize: bottom [C, H*W] -> g_featT [H*W, C]
// 256 threads; write phase: one uint4 (8 channels as 4x half2) per thread,
// chunk-fastest mapping -> fully coalesced 128B store rows.
// -------------------------------------------------------------------------
__global__ __launch_bounds__(256) void transpose_kernel(
    const float* __restrict__ in) {
    __shared__ float tile[64][33];
    int hw0 = blockIdx.x * 32;
    int c0  = blockIdx.y * 64;
    int tx = threadIdx.x, ty = threadIdx.y;   // (32, 8)

    int hw = hw0 + tx;
    #pragma unroll
    for (int j = 0; j < 8; j++) {
        int c = c0 + ty * 8 + j;
        if (hw < HW_DIM) tile[ty * 8 + j][tx] = in[c * HW_DIM + hw];
    }
    __syncthreads();

    int t     = ty * 32 + tx;
    int hwi   = t >> 3;          // 0..31
    int chunk = t & 7;           // 0..7  (fastest -> coalesced)
    int hww   = hw0 + hwi;
    if (hww < HW_DIM) {
        float f0 = tile[chunk * 8 + 0][hwi];
        float f1 = tile[chunk * 8 + 1][hwi];
        float f2 = tile[chunk * 8 + 2][hwi];
        float f3 = tile[chunk * 8 + 3][hwi];
        float f4 = tile[chunk * 8 + 4][hwi];
        float f5 = tile[chunk * 8 + 5][hwi];
        float f6 = tile[chunk * 8 + 6][hwi];
        float f7 = tile[chunk * 8 + 7][hwi];
        __half2 h0 = __floats2half2_rn(f0, f1);
        __half2 h1 = __floats2half2_rn(f2, f3);
        __half2 h2 = __floats2half2_rn(f4, f5);
        __half2 h3 = __floats2half2_rn(f6, f7);
        uint4 pk;
        pk.x = *reinterpret_cast<unsigned int*>(&h0);
        pk.y = *reinterpret_cast<unsigned int*>(&h1);
        pk.z = *reinterpret_cast<unsigned int*>(&h2);
        pk.w = *reinterpret_cast<unsigned int*>(&h3);
        *reinterpret_cast<uint4*>(&g_featT[hww * C_DIM + c0 + chunk * 8]) = pk;
    }
}

// -------------------------------------------------------------------------
// Main kernel: grid (512 rois, 2 channel-halves), 128 threads (4 warps).
// Lane owns 8 consecutive channels (16B fp16 LDG.128); warp covers a
// 256-channel half; the 4 warps split the 49 output pixels round-robin.
// Corner OFFSETS live in register tables (load issue never waits on LDS);
// corner WEIGHTS are pre-packed half2 quads in smem (consumed post-load).
// -------------------------------------------------------------------------
__global__ __launch_bounds__(128, 7) void roi_pool_kernel(
    const float* __restrict__ rois, float* __restrict__ out) {

    __shared__ float4 tabx[PRE], taby[PRE];
    __shared__ __align__(16) uint4 swt[NSAMP];   // 4x half2 weights per sample
    __shared__ __align__(16) __half stage[49 * PADH];

    const int n = blockIdx.x;
    const int t = threadIdx.x;

    // ---- per-ROI corner tables (threads 0..27) ----
    if (t < 2 * PRE) {
        const int axis = (t >= PRE);          // 0 = x, 1 = y
        const int i = axis ? (t - PRE) : t;
        const float lo = rois[n * 5 + (axis ? 2 : 1)] * (1.0f / 16.0f);
        const float hi = rois[n * 5 + (axis ? 4 : 3)] * (1.0f / 16.0f);
        const int D = axis ? H_DIM : W_DIM;

        // replicate reference math exactly
        float s  = (hi - lo) / (float)(D - 1);
        float tt = (lo + hi - (float)(D - 1)) / (float)(D - 1);
        float base = -1.0f + (float)i * (2.0f / 13.0f);
        float g  = s * base + tt;
        float xc = (g + 1.0f) * 0.5f * (float)(D - 1);

        float f0 = floorf(xc);
        int   i0 = (int)f0;
        float w1 = xc - f0;
        float w0 = 1.0f - w1;
        float v0 = (i0 >= 0 && i0 <= D - 1) ? 1.0f : 0.0f;
        float v1 = (i0 + 1 >= 0 && i0 + 1 <= D - 1) ? 1.0f : 0.0f;
        int c0 = min(max(i0, 0), D - 1);
        int c1 = min(max(i0 + 1, 0), D - 1);

        int mul = axis ? (W_DIM * (C_DIM / 8)) : (C_DIM / 8);
        float4 e;
        e.x = __int_as_float(c0 * mul);
        e.y = __int_as_float(c1 * mul);
        e.z = w0 * v0;
        e.w = w1 * v1;
        if (axis) taby[i] = e; else tabx[i] = e;
    }
    __syncthreads();

    // ---- pre-pack per-sample corner weight quads (fp32 products -> half2)
    for (int s = t; s < NSAMP; s += 128) {
        int sy = s / PRE;
        int sx = s - sy * PRE;
        float4 tyv = taby[sy];
        float4 txv = tabx[sx];
        __half2 w00 = __float2half2_rn(tyv.z * txv.z);
        __half2 w01 = __float2half2_rn(tyv.z * txv.w);
        __half2 w10 = __float2half2_rn(tyv.w * txv.z);
        __half2 w11 = __float2half2_rn(tyv.w * txv.w);
        uint4 pk;
        pk.x = *reinterpret_cast<unsigned int*>(&w00);
        pk.y = *reinterpret_cast<unsigned int*>(&w01);
        pk.z = *reinterpret_cast<unsigned int*>(&w10);
        pk.w = *reinterpret_cast<unsigned int*>(&w11);
        swt[s] = pk;
    }
    __syncthreads();

    const int w    = t >> 5;
    const int lane = t & 31;
    const uint4* __restrict__ fb =
        (const uint4*)g_featT + blockIdx.y * 32 + lane;

    const __half2 HMIN = __float2half2_rn(-60000.0f);

    for (int p = w; p < 49; p += 4) {
        const int py = p / 7;
        const int px = p - py * 7;
        const int s0 = (2 * py) * PRE + 2 * px;

        const float4 tx0 = tabx[2 * px];
        const float4 tx1 = tabx[2 * px + 1];
        const float4 ty0 = taby[2 * py];
        const float4 ty1 = taby[2 * py + 1];

        __half2 m0 = HMIN, m1 = HMIN, m2 = HMIN, m3 = HMIN;

        #pragma unroll
        for (int dy = 0; dy < 2; dy++) {
            const float4 ty = dy ? ty1 : ty0;
            const int oy0 = __float_as_int(ty.x);
            const int oy1 = __float_as_int(ty.y);
            #pragma unroll
            for (int dx = 0; dx < 2; dx++) {
                const float4 tx = dx ? tx1 : tx0;
                const int ox0 = __float_as_int(tx.x);
                const int ox1 = __float_as_int(tx.y);

                // 4 independent 16B gathers (8 fp16 channels each)
                uint4 r00 = fb[oy0 + ox0];
                uint4 r01 = fb[oy0 + ox1];
                uint4 r10 = fb[oy1 + ox0];
                uint4 r11 = fb[oy1 + ox1];

                // pre-packed corner weights (broadcast LDS.128)
                const uint4 wq = swt[s0 + dy * PRE + dx];
                const __half2 w00 = *reinterpret_cast<const __half2*>(&wq.x);
                const __half2 w01 = *reinterpret_cast<const __half2*>(&wq.y);
                const __half2 w10 = *reinterpret_cast<const __half2*>(&wq.z);
                const __half2 w11 = *reinterpret_cast<const __half2*>(&wq.w);

                const __half2* h00 = reinterpret_cast<const __half2*>(&r00);
                const __half2* h01 = reinterpret_cast<const __half2*>(&r01);
                const __half2* h10 = reinterpret_cast<const __half2*>(&r10);
                const __half2* h11 = reinterpret_cast<const __half2*>(&r11);

                __half2 v0 = __hmul2(h00[0], w00);
                __half2 v1 = __hmul2(h00[1], w00);
                __half2 v2 = __hmul2(h00[2], w00);
                __half2 v3 = __hmul2(h00[3], w00);
                v0 = __hfma2(h01[0], w01, v0);
                v1 = __hfma2(h01[1], w01, v1);
                v2 = __hfma2(h01[2], w01, v2);
                v3 = __hfma2(h01[3], w01, v3);
                v0 = __hfma2(h10[0], w10, v0);
                v1 = __hfma2(h10[1], w10, v1);
                v2 = __hfma2(h10[2], w10, v2);
                v3 = __hfma2(h10[3], w10, v3);
                v0 = __hfma2(h11[0], w11, v0);
                v1 = __hfma2(h11[1], w11, v1);
                v2 = __hfma2(h11[2], w11, v2);
                v3 = __hfma2(h11[3], w11, v3);

                m0 = __hmax2(m0, v0);
                m1 = __hmax2(m1, v1);
                m2 = __hmax2(m2, v2);
                m3 = __hmax2(m3, v3);
            }
        }

        // pixel-major fp16 stage: 16B STS, lane-consecutive -> conflict-free
        uint4 pk;
        pk.x = *reinterpret_cast<unsigned int*>(&m0);
        pk.y = *reinterpret_cast<unsigned int*>(&m1);
        pk.z = *reinterpret_cast<unsigned int*>(&m2);
        pk.w = *reinterpret_cast<unsigned int*>(&m3);
        *reinterpret_cast<uint4*>(&stage[p * PADH + lane * 8]) = pk;
    }
    __syncthreads();

    // ---- coalesced writeback: thread handles a channel PAIR (2c, 2c+1) at
    // pixel p via one LDS.32; both STG streams coalesced. 6272 pairs total,
    // pair index = t + k*128 walked incrementally (p fastest, 128 = 2*49+30).
    float* __restrict__ ob = out + (size_t)n * (C_DIM * 49)
                                 + (size_t)blockIdx.y * (256 * 49);
    int c2 = t / 49;
    int p  = t - c2 * 49;
    #pragma unroll 7
    for (int k = 0; k < 49; k++) {
        unsigned int v =
            *reinterpret_cast<const unsigned int*>(&stage[p * PADH + 2 * c2]);
        __half2 h = *reinterpret_cast<__half2*>(&v);
        float2 f = __half22float2(h);
        ob[(2 * c2) * 49 + p]     = f.x;
        ob[(2 * c2 + 1) * 49 + p] = f.y;
        p += 30; c2 += 2;             // advance by 128 = 2*49 + 30
        if (p >= 49) { p -= 49; c2 += 1; }
    }
}

// -------------------------------------------------------------------------
extern "C" void kernel_launch(void* const* d_in, const int* in_sizes, int n_in,
                              void* d_out, int out_size) {
    const float* bottom = (const float*)d_in[0];
    const float* rois   = (const float*)d_in[1];
    if (n_in >= 2 && in_sizes[0] == NROI * 5) {
        bottom = (const float*)d_in[1];
        rois   = (const float*)d_in[0];
    }
    float* out = (float*)d_out;

    dim3 tgrid((HW_DIM + 31) / 32, C_DIM / 64);
    transpose_kernel<<<tgrid, dim3(32, 8)>>>(bottom);

    dim3 rgrid(NROI, 2);
    roi_pool_kernel<<<rgrid, 128>>>(rois, out);
}

// round 13
// speedup vs baseline: 1.6107x; 1.0716x over previous
#include <cuda_runtime.h>
#include <cuda_fp16.h>
#include <float.h>

#define C_DIM 512
#define H_DIM 50
#define W_DIM 75
#define HW_DIM (H_DIM * W_DIM)
#define NROI 512
#define PRE 14
#define PADH 264   // stage row stride in halves (= 528B, 16B-aligned)

// channels-last fp16 copy of the feature map: [H*W, C]
__device__ __align__(16) __half g_featT[HW_DIM * C_DIM];

// -------------------------------------------------------------------------
// Tiled transpose + fp16 quantize: bottom [C, H*W] -> g_featT [H*W, C]
// Block covers 64 channels x 32 hw; stores half2 (coalesced 128B rows).
// -------------------------------------------------------------------------
__global__ void transpose_kernel(const float* __restrict__ in) {
    __shared__ float tile[64][33];
    int hw0 = blockIdx.x * 32;
    int c0  = blockIdx.y * 64;
    int tx = threadIdx.x, ty = threadIdx.y;

    #pragma unroll
    for (int j = 0; j < 64; j += 8) {
        int hw = hw0 + tx;
        int c  = c0 + ty + j;
        if (hw < HW_DIM) tile[ty + j][tx] = in[c * HW_DIM + hw];
    }
    __syncthreads();
    #pragma unroll
    for (int j = 0; j < 32; j += 8) {
        int hw = hw0 + ty + j;
        if (hw < HW_DIM) {
            __half2 v = __floats2half2_rn(tile[2 * tx][ty + j],
                                          tile[2 * tx + 1][ty + j]);
            *reinterpret_cast<__half2*>(&g_featT[hw * C_DIM + c0 + 2 * tx]) = v;
        }
    }
}

// -------------------------------------------------------------------------
// Main kernel: grid (512 rois, 2 channel-halves), 128 threads (4 warps).
// Lane owns 8 consecutive channels (16B fp16 LDG.128 = 4 half2); warp covers
// a 256-channel half; the 4 warps split the 49 output pixels round-robin.
// Bilinear sample = corner-sum in half2 with fp32-computed corner weights.
// R9 hot loop verbatim: offsets+weights in registers, 4x4-load batches.
// -------------------------------------------------------------------------
__global__ __launch_bounds__(128, 7) void roi_pool_kernel(
    const float* __restrict__ rois, float* __restrict__ out) {

    // Packed corner tables: (.x = off0 bits, .y = off1 bits, .z = w0, .w = w1),
    // offsets in 8-channel (uint4) units.
    __shared__ float4 tabx[PRE], taby[PRE];
    __shared__ __align__(16) __half stage[49 * PADH];

    const int n = blockIdx.x;
    const int t = threadIdx.x;

    // ---- per-ROI corner tables (threads 0..27) ----
    if (t < 2 * PRE) {
        const int axis = (t >= PRE);          // 0 = x, 1 = y
        const int i = axis ? (t - PRE) : t;
        const float lo = rois[n * 5 + (axis ? 2 : 1)] * (1.0f / 16.0f);
        const float hi = rois[n * 5 + (axis ? 4 : 3)] * (1.0f / 16.0f);
        const int D = axis ? H_DIM : W_DIM;

        // replicate reference math exactly
        float s  = (hi - lo) / (float)(D - 1);
        float tt = (lo + hi - (float)(D - 1)) / (float)(D - 1);
        float base = -1.0f + (float)i * (2.0f / 13.0f);
        float g  = s * base + tt;
        float xc = (g + 1.0f) * 0.5f * (float)(D - 1);

        float f0 = floorf(xc);
        int   i0 = (int)f0;
        float w1 = xc - f0;
        float w0 = 1.0f - w1;
        float v0 = (i0 >= 0 && i0 <= D - 1) ? 1.0f : 0.0f;
        float v1 = (i0 + 1 >= 0 && i0 + 1 <= D - 1) ? 1.0f : 0.0f;
        int c0 = min(max(i0, 0), D - 1);
        int c1 = min(max(i0 + 1, 0), D - 1);

        int mul = axis ? (W_DIM * (C_DIM / 8)) : (C_DIM / 8);
        float4 e;
        e.x = __int_as_float(c0 * mul);
        e.y = __int_as_float(c1 * mul);
        e.z = w0 * v0;
        e.w = w1 * v1;
        if (axis) taby[i] = e; else tabx[i] = e;
    }
    __syncthreads();

    const int w    = t >> 5;
    const int lane = t & 31;
    const uint4* __restrict__ fb =
        (const uint4*)g_featT + blockIdx.y * 32 + lane;

    const __half2 HMIN = __float2half2_rn(-60000.0f);

    for (int p = w; p < 49; p += 4) {
        const int py = p / 7;
        const int px = p - py * 7;

        const float4 tx0 = tabx[2 * px];
        const float4 tx1 = tabx[2 * px + 1];
        const float4 ty0 = taby[2 * py];
        const float4 ty1 = taby[2 * py + 1];

        __half2 m0 = HMIN, m1 = HMIN, m2 = HMIN, m3 = HMIN;

        #pragma unroll
        for (int dy = 0; dy < 2; dy++) {
            const float4 ty = dy ? ty1 : ty0;
            const int oy0 = __float_as_int(ty.x);
            const int oy1 = __float_as_int(ty.y);
            const float wy0 = ty.z, wy1 = ty.w;
            #pragma unroll
            for (int dx = 0; dx < 2; dx++) {
                const float4 tx = dx ? tx1 : tx0;
                const int ox0 = __float_as_int(tx.x);
                const int ox1 = __float_as_int(tx.y);

                // 4 independent 16B gathers (8 fp16 channels each)
                uint4 r00 = fb[oy0 + ox0];
                uint4 r01 = fb[oy0 + ox1];
                uint4 r10 = fb[oy1 + ox0];
                uint4 r11 = fb[oy1 + ox1];

                // corner weights: fp32 products, broadcast to half2
                const float wx0 = tx.z, wx1 = tx.w;
                const __half2 w00 = __float2half2_rn(wy0 * wx0);
                const __half2 w01 = __float2half2_rn(wy0 * wx1);
                const __half2 w10 = __float2half2_rn(wy1 * wx0);
                const __half2 w11 = __float2half2_rn(wy1 * wx1);

                const __half2* h00 = reinterpret_cast<const __half2*>(&r00);
                const __half2* h01 = reinterpret_cast<const __half2*>(&r01);
                const __half2* h10 = reinterpret_cast<const __half2*>(&r10);
                const __half2* h11 = reinterpret_cast<const __half2*>(&r11);

                __half2 v0 = __hmul2(h00[0], w00);
                __half2 v1 = __hmul2(h00[1], w00);
                __half2 v2 = __hmul2(h00[2], w00);
                __half2 v3 = __hmul2(h00[3], w00);
                v0 = __hfma2(h01[0], w01, v0);
                v1 = __hfma2(h01[1], w01, v1);
                v2 = __hfma2(h01[2], w01, v2);
                v3 = __hfma2(h01[3], w01, v3);
                v0 = __hfma2(h10[0], w10, v0);
                v1 = __hfma2(h10[1], w10, v1);
                v2 = __hfma2(h10[2], w10, v2);
                v3 = __hfma2(h10[3], w10, v3);
                v0 = __hfma2(h11[0], w11, v0);
                v1 = __hfma2(h11[1], w11, v1);
                v2 = __hfma2(h11[2], w11, v2);
                v3 = __hfma2(h11[3], w11, v3);

                m0 = __hmax2(m0, v0);
                m1 = __hmax2(m1, v1);
                m2 = __hmax2(m2, v2);
                m3 = __hmax2(m3, v3);
            }
        }

        // pixel-major fp16 stage: 16B STS, lane-consecutive -> conflict-free
        uint4 pk;
        pk.x = *reinterpret_cast<unsigned int*>(&m0);
        pk.y = *reinterpret_cast<unsigned int*>(&m1);
        pk.z = *reinterpret_cast<unsigned int*>(&m2);
        pk.w = *reinterpret_cast<unsigned int*>(&m3);
        *reinterpret_cast<uint4*>(&stage[p * PADH + lane * 8]) = pk;
    }
    __syncthreads();

    // ---- coalesced writeback: thread handles a channel PAIR (2c, 2c+1) at
    // pixel p via one LDS.32; both STG streams coalesced. 6272 pairs total,
    // pair index = t + k*128 walked incrementally (p fastest, 128 = 2*49+30).
    float* __restrict__ ob = out + (size_t)n * (C_DIM * 49)
                                 + (size_t)blockIdx.y * (256 * 49);
    int c2 = t / 49;
    int p  = t - c2 * 49;
    #pragma unroll 7
    for (int k = 0; k < 49; k++) {
        unsigned int v =
            *reinterpret_cast<const unsigned int*>(&stage[p * PADH + 2 * c2]);
        __half2 h = *reinterpret_cast<__half2*>(&v);
        float2 f = __half22float2(h);
        ob[(2 * c2) * 49 + p]     = f.x;
        ob[(2 * c2 + 1) * 49 + p] = f.y;
        p += 30; c2 += 2;             // advance by 128 = 2*49 + 30
        if (p >= 49) { p -= 49; c2 += 1; }
    }
}

// -------------------------------------------------------------------------
extern "C" void kernel_launch(void* const* d_in, const int* in_sizes, int n_in,
                              void* d_out, int out_size) {
    const float* bottom = (const float*)d_in[0];
    const float* rois   = (const float*)d_in[1];
    if (n_in >= 2 && in_sizes[0] == NROI * 5) {
        bottom = (const float*)d_in[1];
        rois   = (const float*)d_in[0];
    }
    float* out = (float*)d_out;

    dim3 tgrid((HW_DIM + 31) / 32, C_DIM / 64);
    transpose_kernel<<<tgrid, dim3(32, 8)>>>(bottom);

    dim3 rgrid(NROI, 2);
    roi_pool_kernel<<<rgrid, 128>>>(rois, out);
}

// round 14
// speedup vs baseline: 1.6231x; 1.0077x over previous
#include <cuda_runtime.h>
#include <cuda_fp16.h>
#include <float.h>

#define C_DIM 512
#define H_DIM 50
#define W_DIM 75
#define HW_DIM (H_DIM * W_DIM)
#define NROI 512
#define PRE 14
#define PADH 264   // stage row stride in halves (= 528B, 16B-aligned)

// channels-last fp16 copy of the feature map: [H*W, C]
__device__ __align__(16) __half g_featT[HW_DIM * C_DIM];

// -------------------------------------------------------------------------
// Tiled transpose + fp16 quantize: bottom [C, H*W] -> g_featT [H*W, C]
// -------------------------------------------------------------------------
__global__ void transpose_kernel(const float* __restrict__ in) {
    __shared__ float tile[64][33];
    int hw0 = blockIdx.x * 32;
    int c0  = blockIdx.y * 64;
    int tx = threadIdx.x, ty = threadIdx.y;

    #pragma unroll
    for (int j = 0; j < 64; j += 8) {
        int hw = hw0 + tx;
        int c  = c0 + ty + j;
        if (hw < HW_DIM) tile[ty + j][tx] = in[c * HW_DIM + hw];
    }
    __syncthreads();
    #pragma unroll
    for (int j = 0; j < 32; j += 8) {
        int hw = hw0 + ty + j;
        if (hw < HW_DIM) {
            __half2 v = __floats2half2_rn(tile[2 * tx][ty + j],
                                          tile[2 * tx + 1][ty + j]);
            *reinterpret_cast<__half2*>(&g_featT[hw * C_DIM + c0 + 2 * tx]) = v;
        }
    }
}

// -------------------------------------------------------------------------
// Main kernel: grid (512 rois, 2 channel-halves), 128 threads (4 warps).
// Lane owns 8 consecutive channels (16B fp16 LDG.128); warp covers a
// 256-channel half; warps split the pixels round-robin. The 49 pixels are
// processed in TWO chunks (25 + 24) so the stage is 13.2KB instead of 26KB,
// leaving ~133KB of L1D carveout for the gather working set (vs ~46KB).
// R9 hot loop verbatim: offsets+weights in registers, 4x4-load batches.
// -------------------------------------------------------------------------
__global__ __launch_bounds__(128, 7) void roi_pool_kernel(
    const float* __restrict__ rois, float* __restrict__ out) {

    // Packed corner tables: (.x = off0 bits, .y = off1 bits, .z = w0, .w = w1),
    // offsets in 8-channel (uint4) units.
    __shared__ float4 tabx[PRE], taby[PRE];
    __shared__ __align__(16) __half stage[25 * PADH];

    const int n = blockIdx.x;
    const int t = threadIdx.x;

    // ---- per-ROI corner tables (threads 0..27) ----
    if (t < 2 * PRE) {
        const int axis = (t >= PRE);          // 0 = x, 1 = y
        const int i = axis ? (t - PRE) : t;
        const float lo = rois[n * 5 + (axis ? 2 : 1)] * (1.0f / 16.0f);
        const float hi = rois[n * 5 + (axis ? 4 : 3)] * (1.0f / 16.0f);
        const int D = axis ? H_DIM : W_DIM;

        // replicate reference math exactly
        float s  = (hi - lo) / (float)(D - 1);
        float tt = (lo + hi - (float)(D - 1)) / (float)(D - 1);
        float base = -1.0f + (float)i * (2.0f / 13.0f);
        float g  = s * base + tt;
        float xc = (g + 1.0f) * 0.5f * (float)(D - 1);

        float f0 = floorf(xc);
        int   i0 = (int)f0;
        float w1 = xc - f0;
        float w0 = 1.0f - w1;
        float v0 = (i0 >= 0 && i0 <= D - 1) ? 1.0f : 0.0f;
        float v1 = (i0 + 1 >= 0 && i0 + 1 <= D - 1) ? 1.0f : 0.0f;
        int c0 = min(max(i0, 0), D - 1);
        int c1 = min(max(i0 + 1, 0), D - 1);

        int mul = axis ? (W_DIM * (C_DIM / 8)) : (C_DIM / 8);
        float4 e;
        e.x = __int_as_float(c0 * mul);
        e.y = __int_as_float(c1 * mul);
        e.z = w0 * v0;
        e.w = w1 * v1;
        if (axis) taby[i] = e; else tabx[i] = e;
    }
    __syncthreads();

    const int w    = t >> 5;
    const int lane = t & 31;
    const uint4* __restrict__ fb =
        (const uint4*)g_featT + blockIdx.y * 32 + lane;

    const __half2 HMIN = __float2half2_rn(-60000.0f);

    float* __restrict__ ob = out + (size_t)n * (C_DIM * 49)
                                 + (size_t)blockIdx.y * (256 * 49);

    #pragma unroll
    for (int chunk = 0; chunk < 2; chunk++) {
        const int pb = chunk * 25;
        const int np = chunk ? 24 : 25;

        // ---- compute this chunk's pixels ----
        for (int p = pb + w; p < pb + np; p += 4) {
            const int py = p / 7;
            const int px = p - py * 7;

            const float4 tx0 = tabx[2 * px];
            const float4 tx1 = tabx[2 * px + 1];
            const float4 ty0 = taby[2 * py];
            const float4 ty1 = taby[2 * py + 1];

            __half2 m0 = HMIN, m1 = HMIN, m2 = HMIN, m3 = HMIN;

            #pragma unroll
            for (int dy = 0; dy < 2; dy++) {
                const float4 ty = dy ? ty1 : ty0;
                const int oy0 = __float_as_int(ty.x);
                const int oy1 = __float_as_int(ty.y);
                const float wy0 = ty.z, wy1 = ty.w;
                #pragma unroll
                for (int dx = 0; dx < 2; dx++) {
                    const float4 tx = dx ? tx1 : tx0;
                    const int ox0 = __float_as_int(tx.x);
                    const int ox1 = __float_as_int(tx.y);

                    // 4 independent 16B gathers (8 fp16 channels each)
                    uint4 r00 = fb[oy0 + ox0];
                    uint4 r01 = fb[oy0 + ox1];
                    uint4 r10 = fb[oy1 + ox0];
                    uint4 r11 = fb[oy1 + ox1];

                    // corner weights: fp32 products, broadcast to half2
                    const float wx0 = tx.z, wx1 = tx.w;
                    const __half2 w00 = __float2half2_rn(wy0 * wx0);
                    const __half2 w01 = __float2half2_rn(wy0 * wx1);
                    const __half2 w10 = __float2half2_rn(wy1 * wx0);
                    const __half2 w11 = __float2half2_rn(wy1 * wx1);

                    const __half2* h00 = reinterpret_cast<const __half2*>(&r00);
                    const __half2* h01 = reinterpret_cast<const __half2*>(&r01);
                    const __half2* h10 = reinterpret_cast<const __half2*>(&r10);
                    const __half2* h11 = reinterpret_cast<const __half2*>(&r11);

                    __half2 v0 = __hmul2(h00[0], w00);
                    __half2 v1 = __hmul2(h00[1], w00);
                    __half2 v2 = __hmul2(h00[2], w00);
                    __half2 v3 = __hmul2(h00[3], w00);
                    v0 = __hfma2(h01[0], w01, v0);
                    v1 = __hfma2(h01[1], w01, v1);
                    v2 = __hfma2(h01[2], w01, v2);
                    v3 = __hfma2(h01[3], w01, v3);
                    v0 = __hfma2(h10[0], w10, v0);
                    v1 = __hfma2(h10[1], w10, v1);
                    v2 = __hfma2(h10[2], w10, v2);
                    v3 = __hfma2(h10[3], w10, v3);
                    v0 = __hfma2(h11[0], w11, v0);
                    v1 = __hfma2(h11[1], w11, v1);
                    v2 = __hfma2(h11[2], w11, v2);
                    v3 = __hfma2(h11[3], w11, v3);

                    m0 = __hmax2(m0, v0);
                    m1 = __hmax2(m1, v1);
                    m2 = __hmax2(m2, v2);
                    m3 = __hmax2(m3, v3);
                }
            }

            // pixel-major fp16 stage: 16B STS, lane-consecutive -> conflict-free
            uint4 pk;
            pk.x = *reinterpret_cast<unsigned int*>(&m0);
            pk.y = *reinterpret_cast<unsigned int*>(&m1);
            pk.z = *reinterpret_cast<unsigned int*>(&m2);
            pk.w = *reinterpret_cast<unsigned int*>(&m3);
            *reinterpret_cast<uint4*>(&stage[(p - pb) * PADH + lane * 8]) = pk;
        }
        __syncthreads();

        // ---- coalesced writeback of this chunk: 128 channel-pairs x np
        // pixels; pair index = t + k*128 walked incrementally (p fastest).
        const int q = 128 / np;          // 5 for both np=25 and np=24
        const int r = 128 - q * np;      // 3 / 8
        int c2 = t / np;
        int pp = t - c2 * np;
        for (int k = 0; k < np; k++) {
            unsigned int v = *reinterpret_cast<const unsigned int*>(
                &stage[pp * PADH + 2 * c2]);
            __half2 h = *reinterpret_cast<__half2*>(&v);
            float2 f = __half22float2(h);
            ob[(2 * c2) * 49 + pb + pp]     = f.x;
            ob[(2 * c2 + 1) * 49 + pb + pp] = f.y;
            pp += r; c2 += q;
            if (pp >= np) { pp -= np; c2 += 1; }
        }
        __syncthreads();
    }
}

// -------------------------------------------------------------------------
extern "C" void kernel_launch(void* const* d_in, const int* in_sizes, int n_in,
                              void* d_out, int out_size) {
    const float* bottom = (const float*)d_in[0];
    const float* rois   = (const float*)d_in[1];
    if (n_in >= 2 && in_sizes[0] == NROI * 5) {
        bottom = (const float*)d_in[1];
        rois   = (const float*)d_in[0];
    }
    float* out = (float*)d_out;

    dim3 tgrid((HW_DIM + 31) / 32, C_DIM / 64);
    transpose_kernel<<<tgrid, dim3(32, 8)>>>(bottom);

    dim3 rgrid(NROI, 2);
    roi_pool_kernel<<<rgrid, 128>>>(rois, out);
}